// round 3
// baseline (speedup 1.0000x reference)
#include <cuda_runtime.h>
#include <cuda_bf16.h>
#include <math.h>

#define B_ 64
#define S_ 256
#define H_ 1024
#define V_ 10000
#define GRU_BLOCKS 128

// ---------------- scratch (device globals; no allocation allowed) ----------------
__device__ float g_emb[B_ * H_];       // embedded inputs
__device__ float g_gi[B_ * 3 * H_];    // input-side gate preactivations (bias pre-init)
__device__ float g_h[2 * H_];          // double-buffered hidden state
__device__ float g_cat[B_ * 2 * H_];   // [rnn_output | context]
__device__ float g_ue[H_];             // W_attn[:, H:2H]^T @ v_attn
__device__ float g_scores[B_ * S_];    // raw scores (softmax recomputed per context block)
__device__ float g_pre[B_ * H_];       // concat preactivation (bias pre-init)
__device__ float g_E[B_ * H_];         // tanh(g_pre), staged once
__device__ unsigned g_bar;             // grid barrier counter

// ---------------- packed f32x2 helpers ----------------
__device__ __forceinline__ unsigned long long pack2(float x, float y) {
    unsigned long long r;
    asm("mov.b64 %0, {%1, %2};" : "=l"(r) : "f"(x), "f"(y));
    return r;
}
__device__ __forceinline__ void fma2(unsigned long long& d, unsigned long long a, unsigned long long b) {
    asm("fma.rn.f32x2 %0, %1, %2, %0;" : "+l"(d) : "l"(a), "l"(b));
}
__device__ __forceinline__ float2 unpack2(unsigned long long v) {
    float2 r;
    asm("mov.b64 {%0, %1}, %2;" : "=f"(r.x), "=f"(r.y) : "l"(v));
    return r;
}

// ---------------- release/acquire grid-barrier primitives ----------------
__device__ __forceinline__ unsigned ld_acq(const unsigned* p) {
    unsigned v;
    asm volatile("ld.acquire.gpu.global.u32 %0, [%1];" : "=r"(v) : "l"(p) : "memory");
    return v;
}
__device__ __forceinline__ void red_rel(unsigned* p) {
    asm volatile("red.release.gpu.global.add.u32 [%0], 1;" :: "l"(p) : "memory");
}

// ---------------- K_pre: all init + embedding + u_e in ONE launch ----------------
__global__ void __launch_bounds__(256) k_pre(const int* __restrict__ seq,
                      const float* __restrict__ last_hidden,
                      const float* __restrict__ emb_table,
                      const float* __restrict__ b_ih,
                      const float* __restrict__ b_concat,
                      const float* __restrict__ b_out,
                      const float* __restrict__ v_attn,
                      const float* __restrict__ W_attn,
                      float* __restrict__ out)
{
    int blk = blockIdx.x, t = threadIdx.x;
    if (blk < 64) {
        int b = blk;
        int row = seq[b];
        ((float4*)(g_emb + b * H_))[t] = ((const float4*)(emb_table + (size_t)row * H_))[t];
        float4* gi4 = (float4*)(g_gi + b * 3 * H_);
        const float4* bi4 = (const float4*)b_ih;
        for (int i = t; i < 768; i += 256) gi4[i] = bi4[i];
        ((float4*)(g_pre + b * H_))[t] = ((const float4*)b_concat)[t];
        ((float4*)(g_cat + b * 2 * H_ + H_))[t] = make_float4(0.f, 0.f, 0.f, 0.f);
    } else if (blk < 128) {
        int b = blk - 64;
        float4* d = (float4*)(out + (size_t)b * V_);
        const float4* bo = (const float4*)b_out;
        for (int i = t; i < V_ / 4; i += 256) d[i] = bo[i];
    } else if (blk == 128) {
        for (int i = t; i < H_; i += 256) g_h[i] = last_hidden[i];
        if (t == 0) g_bar = 0u;
    } else {
        // u_e[k] = sum_h v_attn[h] * W_attn[h][H_+k]; each block owns one 256-wide k chunk
        __shared__ float sv[H_];
        for (int i = t; i < H_; i += 256) sv[i] = v_attn[i];
        __syncthreads();
        int k = (blk - 129) * 256 + t;
        float acc = 0.f;
#pragma unroll 8
        for (int h = 0; h < H_; h++)
            acc = fmaf(sv[h], W_attn[(size_t)h * (2 * H_) + H_ + k], acc);
        g_ue[k] = acc;
    }
}

// ---------------- GEMM: C[b][r] += sum_k W[r][k]*E[b][k], (R/32)x8 regs, fma.f32x2 ----------------
// MODE 0: gi      (E=g_emb ldE=1024, C=g_gi  ldC=3072)
// MODE 1: concat  (E=g_cat ldE=2048, C=g_pre ldC=1024)
// MODE 2: out     (E=g_E   ldE=1024, C=Cout  ldC=10000)
template<int MODE, int R>
__global__ void __launch_bounds__(256) k_gemm(const float* __restrict__ W, int lda,
                                              int Rtot, int Ksplit,
                                              float* __restrict__ Cout)
{
    constexpr int KC = 16;
    constexpr int TR = R / 32;
    const float* E; int ldE; float* C; int ldC;
    if constexpr (MODE == 0) { E = g_emb; ldE = H_;     C = g_gi;  ldC = 3 * H_; }
    else if constexpr (MODE == 1) { E = g_cat; ldE = 2 * H_; C = g_pre; ldC = H_; }
    else { E = g_E; ldE = H_; C = Cout; ldC = V_; }

    __shared__ float sWT[KC][R + 4];     // transposed W tile: [k][row]
    __shared__ float sE[KC][64 + 4];     // [k][batch]

    const int r0 = blockIdx.x * R;
    const int k0 = blockIdx.y * Ksplit;
    const int tcol = threadIdx.x & 7;    // 8 batch groups of 8
    const int trow = threadIdx.x >> 3;   // 32 row groups of TR

    unsigned long long acc2[TR][4];
#pragma unroll
    for (int i = 0; i < TR; i++)
#pragma unroll
        for (int j = 0; j < 4; j++) acc2[i][j] = 0ull;

    for (int kc = k0; kc < k0 + Ksplit; kc += KC) {
        // stage W tile (R rows x 16 k), float4 loads, transposed store
#pragma unroll
        for (int q = 0; q < R * KC / 1024; q++) {
            int idx = threadIdx.x + q * 256;
            int rr = idx >> 2;
            int kq = (idx & 3) * 4;
            int gr = r0 + rr;
            float4 v = (gr < Rtot) ? *(const float4*)&W[(size_t)gr * lda + kc + kq]
                                   : make_float4(0.f, 0.f, 0.f, 0.f);
            sWT[kq + 0][rr] = v.x; sWT[kq + 1][rr] = v.y;
            sWT[kq + 2][rr] = v.z; sWT[kq + 3][rr] = v.w;
        }
        // stage E tile (64 b x 16 k)
        {
            int bb = threadIdx.x >> 2;
            int kq = (threadIdx.x & 3) * 4;
            float4 v = *(const float4*)&E[bb * ldE + kc + kq];
            sE[kq + 0][bb] = v.x; sE[kq + 1][bb] = v.y;
            sE[kq + 2][bb] = v.z; sE[kq + 3][bb] = v.w;
        }
        __syncthreads();
#pragma unroll
        for (int kk = 0; kk < KC; kk++) {
            float a[TR];
#pragma unroll
            for (int q = 0; q < TR; q += 4)
                *(float4*)&a[q] = *(const float4*)&sWT[kk][trow * TR + q];
            ulonglong2 q0 = *(const ulonglong2*)&sE[kk][tcol * 8];
            ulonglong2 q1 = *(const ulonglong2*)&sE[kk][tcol * 8 + 4];
            unsigned long long b2[4] = {q0.x, q0.y, q1.x, q1.y};
#pragma unroll
            for (int i = 0; i < TR; i++) {
                unsigned long long ua = pack2(a[i], a[i]);
#pragma unroll
                for (int j = 0; j < 4; j++) fma2(acc2[i][j], ua, b2[j]);
            }
        }
        __syncthreads();
    }
#pragma unroll
    for (int i = 0; i < TR; i++) {
        int gr = r0 + trow * TR + i;
        if (gr < Rtot) {
#pragma unroll
            for (int j = 0; j < 4; j++) {
                float2 v = unpack2(acc2[i][j]);
                atomicAdd(&C[(size_t)(tcol * 8 + 2 * j) * ldC + gr], v.x);
                atomicAdd(&C[(size_t)(tcol * 8 + 2 * j + 1) * ldC + gr], v.y);
            }
        }
    }
}

// ---------------- persistent GRU recurrence: weights in registers, rel/acq barrier ----------------
__global__ void __launch_bounds__(256) k_gru(const float* __restrict__ W_hh,
                                             const float* __restrict__ b_hh,
                                             float* __restrict__ out)
{
    __shared__ float sH[H_];
    const int t = threadIdx.x, w = t >> 5, lane = t & 31;
    const int j = blockIdx.x * 8 + w;

    // this warp's three weight rows, register-resident (96 floats/lane)
    float4 wr[8], wz[8], wn[8];
    const float4* Wr4 = (const float4*)(W_hh + (size_t)j * H_);
    const float4* Wz4 = (const float4*)(W_hh + (size_t)(H_ + j) * H_);
    const float4* Wn4 = (const float4*)(W_hh + (size_t)(2 * H_ + j) * H_);
#pragma unroll
    for (int i = 0; i < 8; i++) {
        wr[i] = Wr4[lane + i * 32];
        wz[i] = Wz4[lane + i * 32];
        wn[i] = Wn4[lane + i * 32];
    }
    const float bhr = b_hh[j], bhz = b_hh[H_ + j], bhn = b_hh[2 * H_ + j];
    const float4* sH4 = (const float4*)sH;

    for (int b = 0; b < B_; b++) {
        // stage h (bypass L1; written by other SMs)
        ((float4*)sH)[t] = __ldcg((const float4*)(g_h + (b & 1) * H_) + t);
        __syncthreads();

        // hoist gi loads (independent of the dot)
        const float* gib = g_gi + b * 3 * H_;
        float gir = gib[j], giz = gib[H_ + j], gin = gib[2 * H_ + j];

        float ar = 0.f, az = 0.f, an = 0.f;
#pragma unroll
        for (int i = 0; i < 8; i++) {
            float4 h4 = sH4[lane + i * 32];
            ar = fmaf(wr[i].x, h4.x, ar); az = fmaf(wz[i].x, h4.x, az); an = fmaf(wn[i].x, h4.x, an);
            ar = fmaf(wr[i].y, h4.y, ar); az = fmaf(wz[i].y, h4.y, az); an = fmaf(wn[i].y, h4.y, an);
            ar = fmaf(wr[i].z, h4.z, ar); az = fmaf(wz[i].z, h4.z, az); an = fmaf(wn[i].z, h4.z, an);
            ar = fmaf(wr[i].w, h4.w, ar); az = fmaf(wz[i].w, h4.w, az); an = fmaf(wn[i].w, h4.w, an);
        }
#pragma unroll
        for (int off = 16; off; off >>= 1) {
            ar += __shfl_down_sync(0xffffffffu, ar, off);
            az += __shfl_down_sync(0xffffffffu, az, off);
            an += __shfl_down_sync(0xffffffffu, an, off);
        }
        if (lane == 0) {
            // fast activations on the serial critical path (err ~1e-6, budget 1e-3)
            float r = 1.f / (1.f + __expf(-(gir + ar + bhr)));
            float z = 1.f / (1.f + __expf(-(giz + az + bhz)));
            float narg = gin + r * (an + bhn);
            float n = 2.f / (1.f + __expf(-2.f * narg)) - 1.f;   // tanh
            float hp = sH[j];
            float hn = (1.f - z) * n + z * hp;
            g_h[((b + 1) & 1) * H_ + j] = hn;
            g_cat[b * 2 * H_ + j] = hn;
            if (b == B_ - 1) out[B_ * V_ + j] = hn;   // hidden output
        }
        if (b == B_ - 1) break;                        // no barrier after last step
        __syncthreads();                               // all stores done before release
        if (t == 0) {
            red_rel(&g_bar);                           // release: publishes block's h stores
            unsigned target = (unsigned)(b + 1) * GRU_BLOCKS;
            while (ld_acq(&g_bar) < target) { }        // acquire: sees peers' h stores
        }
        __syncthreads();
    }
}

// ---------------- attention scores: scores[b][s] = enc[s][b][:] . u_e ----------------
__global__ void __launch_bounds__(256) k_scores(const float* __restrict__ enc)
{
    __shared__ float su[H_];
    for (int i = threadIdx.x; i < H_; i += 256) su[i] = g_ue[i];
    __syncthreads();
    int w = threadIdx.x >> 5, lane = threadIdx.x & 31;
    int gw = blockIdx.x * 8 + w;      // 0..16383
    int b = gw >> 8, s = gw & 255;
    const float4* p = (const float4*)(enc + (size_t)s * (B_ * H_) + b * H_);
    const float4* su4 = (const float4*)su;
    float acc[4] = {0.f, 0.f, 0.f, 0.f};
#pragma unroll
    for (int i = 0; i < 8; i++) {
        float4 x = __ldcg(p + lane + i * 32);
        float4 u = su4[lane + i * 32];
        acc[i & 3] = fmaf(x.x, u.x, acc[i & 3]);
        acc[i & 3] = fmaf(x.y, u.y, acc[i & 3]);
        acc[i & 3] = fmaf(x.z, u.z, acc[i & 3]);
        acc[i & 3] = fmaf(x.w, u.w, acc[i & 3]);
    }
    float a = (acc[0] + acc[1]) + (acc[2] + acc[3]);
#pragma unroll
    for (int off = 16; off; off >>= 1) a += __shfl_down_sync(0xffffffffu, a, off);
    if (lane == 0) g_scores[b * S_ + s] = a;
}

// ---------------- context (softmax fused): ctx[b][h] += sum_s softmax(scores)[b][s]*enc[s][b][h] ----------------
__global__ void __launch_bounds__(256) k_context(const float* __restrict__ enc,
                                                 float* __restrict__ out)
{
    int bx = blockIdx.x;
    int b = bx >> 3, hc = (bx >> 1) & 3, sh = bx & 1;
    int t = threadIdx.x;
    __shared__ float sw_[S_];
    __shared__ float red[256];

    // recompute softmax locally (g_scores is tiny + L2-hot)
    float v = g_scores[b * S_ + t];
    red[t] = v; __syncthreads();
    for (int o = 128; o; o >>= 1) { if (t < o) red[t] = fmaxf(red[t], red[t + o]); __syncthreads(); }
    float m = red[0]; __syncthreads();
    float e = __expf(v - m);
    red[t] = e; __syncthreads();
    for (int o = 128; o; o >>= 1) { if (t < o) red[t] += red[t + o]; __syncthreads(); }
    float wgt = e / red[0];
    sw_[t] = wgt;
    if (hc == 0 && sh == 0) out[B_ * V_ + H_ + b * S_ + t] = wgt;  // attn_weights output
    __syncthreads();

    int h = hc * 256 + t;
    const float* p = enc + b * H_ + h;
    int s0 = sh * 128;
    float a0 = 0.f, a1 = 0.f, a2 = 0.f, a3 = 0.f;
#pragma unroll 4
    for (int s = s0; s < s0 + 128; s += 4) {
        a0 = fmaf(sw_[s + 0], __ldcg(p + (size_t)(s + 0) * (B_ * H_)), a0);
        a1 = fmaf(sw_[s + 1], __ldcg(p + (size_t)(s + 1) * (B_ * H_)), a1);
        a2 = fmaf(sw_[s + 2], __ldcg(p + (size_t)(s + 2) * (B_ * H_)), a2);
        a3 = fmaf(sw_[s + 3], __ldcg(p + (size_t)(s + 3) * (B_ * H_)), a3);
    }
    atomicAdd(&g_cat[b * 2 * H_ + H_ + h], (a0 + a1) + (a2 + a3));
}

// ---------------- tanh staging: g_E = tanh(g_pre), computed once ----------------
__global__ void __launch_bounds__(256) k_tanh()
{
    int idx = blockIdx.x * 256 + threadIdx.x;     // 16384 float4s
    float4 v = ((const float4*)g_pre)[idx];
    v.x = tanhf(v.x); v.y = tanhf(v.y); v.z = tanhf(v.z); v.w = tanhf(v.w);
    ((float4*)g_E)[idx] = v;
}

extern "C" void kernel_launch(void* const* d_in, const int* in_sizes, int n_in,
                              void* d_out, int out_size)
{
    const int*   seq         = (const int*)d_in[0];
    const float* last_hidden = (const float*)d_in[1];
    const float* enc         = (const float*)d_in[2];
    const float* emb_table   = (const float*)d_in[3];
    const float* W_ih        = (const float*)d_in[4];
    const float* W_hh        = (const float*)d_in[5];
    const float* b_ih        = (const float*)d_in[6];
    const float* b_hh        = (const float*)d_in[7];
    const float* W_attn      = (const float*)d_in[8];
    /* d_in[9] = b_attn: dropped — softmax is shift-invariant */
    const float* v_attn      = (const float*)d_in[10];
    const float* W_concat    = (const float*)d_in[11];
    const float* b_concat    = (const float*)d_in[12];
    const float* W_out       = (const float*)d_in[13];
    const float* b_out       = (const float*)d_in[14];
    float* out = (float*)d_out;

    // all init + embedding + h0 + barrier reset + u_e: ONE launch
    k_pre<<<133, 256>>>(seq, last_hidden, emb_table, b_ih, b_concat, b_out,
                        v_attn, W_attn, out);

    // attention scores (needs only u_e + enc)
    k_scores<<<2048, 256>>>(enc);

    // gi = emb @ W_ih^T (+b_ih pre-init): 24 row-blocks(128) x splitK 16 (k=64) = 384 CTAs
    k_gemm<0, 128><<<dim3(24, 16), 256>>>(W_ih, H_, 3 * H_, 64, nullptr);

    // softmax + context fused: 512 CTAs
    k_context<<<512, 256>>>(enc, out);

    // sequential GRU recurrence (persistent grid, register weights, rel/acq barrier)
    k_gru<<<GRU_BLOCKS, 256>>>(W_hh, b_hh, out);

    // concat preactivation: g_pre += [rnn|ctx] @ W_concat^T: 8 rb x splitK 16 (k=128) = 128 CTAs
    k_gemm<1, 128><<<dim3(8, 16), 256>>>(W_concat, 2 * H_, H_, 128, nullptr);

    // tanh once
    k_tanh<<<64, 256>>>();

    // logits: out += g_E @ W_out^T: 79 rb x splitK 8 (k=128) = 632 CTAs
    k_gemm<2, 128><<<dim3(79, 8), 256>>>(W_out, H_, V_, 128, out);
}

// round 4
// speedup vs baseline: 1.1717x; 1.1717x over previous
#include <cuda_runtime.h>
#include <cuda_bf16.h>
#include <math.h>

#define B_ 64
#define S_ 256
#define H_ 1024
#define V_ 10000
#define GRU_BLOCKS 128

// ---------------- scratch (device globals; no allocation allowed) ----------------
__device__ float g_emb[B_ * H_];        // embedded inputs
__device__ float g_gi[B_ * 3 * H_];     // input-side gate preactivations (bias pre-init)
__device__ float g_h[2 * H_];           // double-buffered hidden state
__device__ float g_cat[B_ * 2 * H_];    // [rnn_output | context]
__device__ float g_ue[H_];              // W_attn[:, H:2H]^T @ v_attn
__device__ float g_scores[B_ * S_];     // raw attention scores
__device__ float g_ctxp[512 * H_];      // per-(b,squad) partial context
__device__ float g_msum[512 * 2];       // per-(b,squad) (max, sum) partials
__device__ float g_pre[B_ * H_];        // concat preactivation (bias pre-init)
__device__ float g_E[B_ * H_];          // tanh(g_pre), staged once
__device__ unsigned g_bar;              // grid barrier counter

// ---------------- packed f32x2 helpers ----------------
__device__ __forceinline__ unsigned long long pack2(float x, float y) {
    unsigned long long r;
    asm("mov.b64 %0, {%1, %2};" : "=l"(r) : "f"(x), "f"(y));
    return r;
}
__device__ __forceinline__ void fma2(unsigned long long& d, unsigned long long a, unsigned long long b) {
    asm("fma.rn.f32x2 %0, %1, %2, %0;" : "+l"(d) : "l"(a), "l"(b));
}
__device__ __forceinline__ float2 unpack2(unsigned long long v) {
    float2 r;
    asm("mov.b64 {%0, %1}, %2;" : "=f"(r.x), "=f"(r.y) : "l"(v));
    return r;
}

// ---------------- release/acquire grid-barrier primitives ----------------
__device__ __forceinline__ unsigned ld_acq(const unsigned* p) {
    unsigned v;
    asm volatile("ld.acquire.gpu.global.u32 %0, [%1];" : "=r"(v) : "l"(p) : "memory");
    return v;
}
__device__ __forceinline__ void red_rel(unsigned* p) {
    asm volatile("red.release.gpu.global.add.u32 [%0], 1;" :: "l"(p) : "memory");
}

// ---------------- K_pre: init + embedding ----------------
__global__ void __launch_bounds__(256) k_pre(const int* __restrict__ seq,
                      const float* __restrict__ last_hidden,
                      const float* __restrict__ emb_table,
                      const float* __restrict__ b_ih,
                      const float* __restrict__ b_concat,
                      const float* __restrict__ b_out,
                      float* __restrict__ out)
{
    int blk = blockIdx.x, t = threadIdx.x;
    if (blk < 64) {
        int b = blk;
        int row = seq[b];
        ((float4*)(g_emb + b * H_))[t] = ((const float4*)(emb_table + (size_t)row * H_))[t];
        float4* gi4 = (float4*)(g_gi + b * 3 * H_);
        const float4* bi4 = (const float4*)b_ih;
        for (int i = t; i < 768; i += 256) gi4[i] = bi4[i];
        ((float4*)(g_pre + b * H_))[t] = ((const float4*)b_concat)[t];
    } else if (blk < 128) {
        int b = blk - 64;
        float4* d = (float4*)(out + (size_t)b * V_);
        const float4* bo = (const float4*)b_out;
        for (int i = t; i < V_ / 4; i += 256) d[i] = bo[i];
    } else {
        for (int i = t; i < H_; i += 256) { g_h[i] = last_hidden[i]; g_ue[i] = 0.f; }
        if (t == 0) g_bar = 0u;
    }
}

// ---------------- u_e[k] = sum_h v_attn[h] * W_attn[h][H_+k]  (h-split + atomics) ----------------
__global__ void __launch_bounds__(256) k_ue(const float* __restrict__ W_attn,
                                            const float* __restrict__ v_attn)
{
    int kb = blockIdx.x & 3;          // 4 k blocks of 256
    int hb = blockIdx.x >> 2;         // 16 h blocks of 64
    int k = kb * 256 + threadIdx.x;
    int h0 = hb * 64;
    float acc = 0.f;
#pragma unroll 8
    for (int h = h0; h < h0 + 64; h++)
        acc = fmaf(v_attn[h], W_attn[(size_t)h * (2 * H_) + H_ + k], acc);
    atomicAdd(&g_ue[k], acc);
}

// ---------------- GEMM: C[b][r] += sum_k W[r][k]*E[b][k], 8x8 regs, fma.f32x2 ----------------
// MODE 0: gi      (E=g_emb ldE=1024, C=g_gi  ldC=3072)
// MODE 1: concat  (E=g_cat ldE=2048, C=g_pre ldC=1024)
// MODE 2: out     (E=g_E   ldE=1024, C=Cout  ldC=10000)
template<int MODE, int R>
__global__ void __launch_bounds__(256) k_gemm(const float* __restrict__ W, int lda,
                                              int Rtot, int Ksplit,
                                              float* __restrict__ Cout)
{
    constexpr int KC = 16;
    constexpr int TR = R / 32;
    const float* E; int ldE; float* C; int ldC;
    if constexpr (MODE == 0) { E = g_emb; ldE = H_;     C = g_gi;  ldC = 3 * H_; }
    else if constexpr (MODE == 1) { E = g_cat; ldE = 2 * H_; C = g_pre; ldC = H_; }
    else { E = g_E; ldE = H_; C = Cout; ldC = V_; }

    __shared__ float sWT[KC][R + 4];     // transposed W tile: [k][row]
    __shared__ float sE[KC][64 + 4];     // [k][batch]

    const int r0 = blockIdx.x * R;
    const int k0 = blockIdx.y * Ksplit;
    const int tcol = threadIdx.x & 7;    // 8 batch groups of 8
    const int trow = threadIdx.x >> 3;   // 32 row groups of TR

    unsigned long long acc2[TR][4];
#pragma unroll
    for (int i = 0; i < TR; i++)
#pragma unroll
        for (int j = 0; j < 4; j++) acc2[i][j] = 0ull;

    for (int kc = k0; kc < k0 + Ksplit; kc += KC) {
        // stage W tile (R rows x 16 k), float4 loads, transposed store
#pragma unroll
        for (int q = 0; q < R * KC / 1024; q++) {
            int idx = threadIdx.x + q * 256;
            int rr = idx >> 2;
            int kq = (idx & 3) * 4;
            int gr = r0 + rr;
            float4 v = (gr < Rtot) ? *(const float4*)&W[(size_t)gr * lda + kc + kq]
                                   : make_float4(0.f, 0.f, 0.f, 0.f);
            sWT[kq + 0][rr] = v.x; sWT[kq + 1][rr] = v.y;
            sWT[kq + 2][rr] = v.z; sWT[kq + 3][rr] = v.w;
        }
        // stage E tile (64 b x 16 k)
        {
            int bb = threadIdx.x >> 2;
            int kq = (threadIdx.x & 3) * 4;
            float4 v = *(const float4*)&E[bb * ldE + kc + kq];
            sE[kq + 0][bb] = v.x; sE[kq + 1][bb] = v.y;
            sE[kq + 2][bb] = v.z; sE[kq + 3][bb] = v.w;
        }
        __syncthreads();
#pragma unroll
        for (int kk = 0; kk < KC; kk++) {
            float a[TR];
#pragma unroll
            for (int q = 0; q < TR; q += 4)
                *(float4*)&a[q] = *(const float4*)&sWT[kk][trow * TR + q];
            ulonglong2 q0 = *(const ulonglong2*)&sE[kk][tcol * 8];
            ulonglong2 q1 = *(const ulonglong2*)&sE[kk][tcol * 8 + 4];
            unsigned long long b2[4] = {q0.x, q0.y, q1.x, q1.y};
#pragma unroll
            for (int i = 0; i < TR; i++) {
                unsigned long long ua = pack2(a[i], a[i]);
#pragma unroll
                for (int j = 0; j < 4; j++) fma2(acc2[i][j], ua, b2[j]);
            }
        }
        __syncthreads();
    }
#pragma unroll
    for (int i = 0; i < TR; i++) {
        int gr = r0 + trow * TR + i;
        if (gr < Rtot) {
#pragma unroll
            for (int j = 0; j < 4; j++) {
                float2 v = unpack2(acc2[i][j]);
                atomicAdd(&C[(size_t)(tcol * 8 + 2 * j) * ldC + gr], v.x);
                atomicAdd(&C[(size_t)(tcol * 8 + 2 * j + 1) * ldC + gr], v.y);
            }
        }
    }
}

// ---------------- persistent GRU recurrence: weights in registers, rel/acq barrier ----------------
__global__ void __launch_bounds__(256) k_gru(const float* __restrict__ W_hh,
                                             const float* __restrict__ b_hh,
                                             float* __restrict__ out)
{
    __shared__ float sH[H_];
    const int t = threadIdx.x, w = t >> 5, lane = t & 31;
    const int j = blockIdx.x * 8 + w;

    // this warp's three weight rows, register-resident (96 floats/lane)
    float4 wr[8], wz[8], wn[8];
    const float4* Wr4 = (const float4*)(W_hh + (size_t)j * H_);
    const float4* Wz4 = (const float4*)(W_hh + (size_t)(H_ + j) * H_);
    const float4* Wn4 = (const float4*)(W_hh + (size_t)(2 * H_ + j) * H_);
#pragma unroll
    for (int i = 0; i < 8; i++) {
        wr[i] = Wr4[lane + i * 32];
        wz[i] = Wz4[lane + i * 32];
        wn[i] = Wn4[lane + i * 32];
    }
    const float bhr = b_hh[j], bhz = b_hh[H_ + j], bhn = b_hh[2 * H_ + j];
    const float4* sH4 = (const float4*)sH;

    // gi for step 0 prefetched before the loop
    float gir = g_gi[j], giz = g_gi[H_ + j], gin = g_gi[2 * H_ + j];

    for (int b = 0; b < B_; b++) {
        // stage h (bypass L1; written by other SMs)
        ((float4*)sH)[t] = __ldcg((const float4*)(g_h + (b & 1) * H_) + t);
        __syncthreads();

        float ar = 0.f, az = 0.f, an = 0.f;
#pragma unroll
        for (int i = 0; i < 8; i++) {
            float4 h4 = sH4[lane + i * 32];
            ar = fmaf(wr[i].x, h4.x, ar); az = fmaf(wz[i].x, h4.x, az); an = fmaf(wn[i].x, h4.x, an);
            ar = fmaf(wr[i].y, h4.y, ar); az = fmaf(wz[i].y, h4.y, az); an = fmaf(wn[i].y, h4.y, an);
            ar = fmaf(wr[i].z, h4.z, ar); az = fmaf(wz[i].z, h4.z, az); an = fmaf(wn[i].z, h4.z, an);
            ar = fmaf(wr[i].w, h4.w, ar); az = fmaf(wz[i].w, h4.w, az); an = fmaf(wn[i].w, h4.w, an);
        }
#pragma unroll
        for (int off = 16; off; off >>= 1) {
            ar += __shfl_down_sync(0xffffffffu, ar, off);
            az += __shfl_down_sync(0xffffffffu, az, off);
            an += __shfl_down_sync(0xffffffffu, an, off);
        }
        if (lane == 0) {
            // fast activations on the serial critical path (err ~1e-6, budget 1e-3)
            float r = 1.f / (1.f + __expf(-(gir + ar + bhr)));
            float z = 1.f / (1.f + __expf(-(giz + az + bhz)));
            float narg = gin + r * (an + bhn);
            float n = 2.f / (1.f + __expf(-2.f * narg)) - 1.f;   // tanh
            float hp = sH[j];
            float hn = (1.f - z) * n + z * hp;
            g_h[((b + 1) & 1) * H_ + j] = hn;
            g_cat[b * 2 * H_ + j] = hn;
            if (b == B_ - 1) out[B_ * V_ + j] = hn;   // hidden output
        }
        if (b == B_ - 1) break;                        // no barrier after last step
        // prefetch next step's gi BEFORE the barrier (off critical path)
        {
            const float* gib = g_gi + (b + 1) * 3 * H_;
            gir = gib[j]; giz = gib[H_ + j]; gin = gib[2 * H_ + j];
        }
        __syncthreads();                               // all stores done before release
        if (t == 0) {
            red_rel(&g_bar);                           // release: publishes block's h stores
            unsigned target = (unsigned)(b + 1) * GRU_BLOCKS;
            while (ld_acq(&g_bar) < target) { }        // acquire: sees peers' h stores
        }
        __syncthreads();
    }
}

// ---------------- single-pass flash attention: partials per (b, squad) ----------------
// grid 512 = b*8 + sq; each block handles 32 s values, reads enc exactly once.
__global__ void __launch_bounds__(256) k_att1(const float* __restrict__ enc)
{
    int bx = blockIdx.x;
    int b = bx >> 3, sq = bx & 7;
    int t = threadIdx.x, w = t >> 5, lane = t & 31;
    int s0 = sq * 32;

    float4 ue = ((const float4*)g_ue)[t];
    float4 ctx = make_float4(0.f, 0.f, 0.f, 0.f);
    float m = -1e30f, sum = 0.f;
    __shared__ float r0s[8], r1s[8];

    const float* base = enc + b * H_;
    for (int s = s0; s < s0 + 32; s += 2) {
        float4 e0 = __ldcg((const float4*)(base + (size_t)s * (B_ * H_)) + t);
        float4 e1 = __ldcg((const float4*)(base + (size_t)(s + 1) * (B_ * H_)) + t);
        float d0 = e0.x * ue.x + e0.y * ue.y + e0.z * ue.z + e0.w * ue.w;
        float d1 = e1.x * ue.x + e1.y * ue.y + e1.z * ue.z + e1.w * ue.w;
#pragma unroll
        for (int off = 16; off; off >>= 1) {
            d0 += __shfl_xor_sync(0xffffffffu, d0, off);
            d1 += __shfl_xor_sync(0xffffffffu, d1, off);
        }
        if (lane == 0) { r0s[w] = d0; r1s[w] = d1; }
        __syncthreads();
        float sc0 = (r0s[0] + r0s[1]) + (r0s[2] + r0s[3]) + (r0s[4] + r0s[5]) + (r0s[6] + r0s[7]);
        float sc1 = (r1s[0] + r1s[1]) + (r1s[2] + r1s[3]) + (r1s[4] + r1s[5]) + (r1s[6] + r1s[7]);
        __syncthreads();
        if (t == 0) g_scores[b * S_ + s] = sc0;
        if (t == 1) g_scores[b * S_ + s + 1] = sc1;
        // online softmax update x2
        float mn = fmaxf(m, sc0);
        float a = __expf(m - mn), w0 = __expf(sc0 - mn);
        sum = sum * a + w0;
        ctx.x = ctx.x * a + w0 * e0.x; ctx.y = ctx.y * a + w0 * e0.y;
        ctx.z = ctx.z * a + w0 * e0.z; ctx.w = ctx.w * a + w0 * e0.w;
        m = mn;
        mn = fmaxf(m, sc1);
        a = __expf(m - mn); float w1 = __expf(sc1 - mn);
        sum = sum * a + w1;
        ctx.x = ctx.x * a + w1 * e1.x; ctx.y = ctx.y * a + w1 * e1.y;
        ctx.z = ctx.z * a + w1 * e1.z; ctx.w = ctx.w * a + w1 * e1.w;
        m = mn;
    }
    ((float4*)(g_ctxp + (size_t)bx * H_))[t] = ctx;
    if (t == 0) { g_msum[bx * 2] = m; g_msum[bx * 2 + 1] = sum; }
}

// ---------------- attention combine: per b, merge 8 partials; write ctx + weights ----------------
__global__ void __launch_bounds__(256) k_att2(float* __restrict__ out)
{
    int b = blockIdx.x, t = threadIdx.x;
    __shared__ float sm_[8], ss_[8];
    if (t < 8) { sm_[t] = g_msum[(b * 8 + t) * 2]; ss_[t] = g_msum[(b * 8 + t) * 2 + 1]; }
    __syncthreads();
    float m = sm_[0];
#pragma unroll
    for (int i = 1; i < 8; i++) m = fmaxf(m, sm_[i]);
    float scl[8]; float S = 0.f;
#pragma unroll
    for (int i = 0; i < 8; i++) { scl[i] = __expf(sm_[i] - m); S = fmaf(ss_[i], scl[i], S); }
    float inv = 1.f / S;

    float4 acc = make_float4(0.f, 0.f, 0.f, 0.f);
#pragma unroll
    for (int i = 0; i < 8; i++) {
        float4 p = ((const float4*)(g_ctxp + (size_t)(b * 8 + i) * H_))[t];
        acc.x = fmaf(p.x, scl[i], acc.x); acc.y = fmaf(p.y, scl[i], acc.y);
        acc.z = fmaf(p.z, scl[i], acc.z); acc.w = fmaf(p.w, scl[i], acc.w);
    }
    acc.x *= inv; acc.y *= inv; acc.z *= inv; acc.w *= inv;
    ((float4*)(g_cat + b * 2 * H_ + H_))[t] = acc;

    // attn_weights output
    float sc = g_scores[b * S_ + t];
    out[B_ * V_ + H_ + b * S_ + t] = __expf(sc - m) * inv;
}

// ---------------- tanh staging: g_E = tanh(g_pre), computed once ----------------
__global__ void __launch_bounds__(256) k_tanh()
{
    int idx = blockIdx.x * 256 + threadIdx.x;     // 16384 float4s
    float4 v = ((const float4*)g_pre)[idx];
    v.x = tanhf(v.x); v.y = tanhf(v.y); v.z = tanhf(v.z); v.w = tanhf(v.w);
    ((float4*)g_E)[idx] = v;
}

extern "C" void kernel_launch(void* const* d_in, const int* in_sizes, int n_in,
                              void* d_out, int out_size)
{
    const int*   seq         = (const int*)d_in[0];
    const float* last_hidden = (const float*)d_in[1];
    const float* enc         = (const float*)d_in[2];
    const float* emb_table   = (const float*)d_in[3];
    const float* W_ih        = (const float*)d_in[4];
    const float* W_hh        = (const float*)d_in[5];
    const float* b_ih        = (const float*)d_in[6];
    const float* b_hh        = (const float*)d_in[7];
    const float* W_attn      = (const float*)d_in[8];
    /* d_in[9] = b_attn: dropped — softmax is shift-invariant */
    const float* v_attn      = (const float*)d_in[10];
    const float* W_concat    = (const float*)d_in[11];
    const float* b_concat    = (const float*)d_in[12];
    const float* W_out       = (const float*)d_in[13];
    const float* b_out       = (const float*)d_in[14];
    float* out = (float*)d_out;

    // 0: init + embedding + h0 + barrier/ue reset
    k_pre<<<129, 256>>>(seq, last_hidden, emb_table, b_ih, b_concat, b_out, out);

    // 1: u_e (parallel h-split version restored)
    k_ue<<<64, 256>>>(W_attn, v_attn);

    // 2: gi = emb @ W_ih^T (+b_ih pre-init): 12 rb(256) x splitK 16 (k=64) = 192 CTAs
    k_gemm<0, 256><<<dim3(12, 16), 256>>>(W_ih, H_, 3 * H_, 64, nullptr);

    // 3: sequential GRU recurrence  <-- ncu profiles launch index 3
    k_gru<<<GRU_BLOCKS, 256>>>(W_hh, b_hh, out);

    // 4-5: single-pass attention (enc read once) + combine
    k_att1<<<512, 256>>>(enc);
    k_att2<<<64, 256>>>(out);

    // 6: concat preactivation: g_pre += [rnn|ctx] @ W_concat^T: 4 rb x splitK 32 (k=64) = 128 CTAs
    k_gemm<1, 256><<<dim3(4, 32), 256>>>(W_concat, 2 * H_, H_, 64, nullptr);

    // 7: tanh once
    k_tanh<<<64, 256>>>();

    // 8: logits: out += g_E @ W_out^T: 40 rb(256) x splitK 8 (k=128) = 320 CTAs
    k_gemm<2, 256><<<dim3(40, 8), 256>>>(W_out, H_, V_, 128, out);
}

// round 5
// speedup vs baseline: 1.1834x; 1.0100x over previous
#include <cuda_runtime.h>
#include <cuda_bf16.h>
#include <math.h>

#define B_ 64
#define S_ 256
#define H_ 1024
#define V_ 10000
#define GRU_BLOCKS 128

// ---------------- scratch (device globals; no allocation allowed) ----------------
__device__ float g_emb[B_ * H_];        // embedded inputs
__device__ float g_gi[B_ * 3 * H_];     // input-side gate preactivations (bias pre-init)
__device__ float g_hrep[8][2][H_];      // hidden state: 8 replicas x double buffer (L2 fan-out relief)
__device__ float g_cat[B_ * 2 * H_];    // [rnn_output | context]
__device__ float g_ue[H_];              // W_attn[:, H:2H]^T @ v_attn
__device__ float g_scores[B_ * S_];     // raw attention scores
__device__ float g_ctxp[512 * H_];      // per-(b,squad) partial context
__device__ float g_msum[512 * 2];       // per-(b,squad) (max, sum) partials
__device__ float g_pre[B_ * H_];        // concat preactivation (bias pre-init)
__device__ float g_E[B_ * H_];          // tanh(g_pre), staged once
__device__ unsigned g_bar;              // grid barrier counter

// ---------------- packed f32x2 helpers ----------------
__device__ __forceinline__ unsigned long long pack2(float x, float y) {
    unsigned long long r;
    asm("mov.b64 %0, {%1, %2};" : "=l"(r) : "f"(x), "f"(y));
    return r;
}
__device__ __forceinline__ void fma2(unsigned long long& d, unsigned long long a, unsigned long long b) {
    asm("fma.rn.f32x2 %0, %1, %2, %0;" : "+l"(d) : "l"(a), "l"(b));
}
__device__ __forceinline__ float2 unpack2(unsigned long long v) {
    float2 r;
    asm("mov.b64 {%0, %1}, %2;" : "=f"(r.x), "=f"(r.y) : "l"(v));
    return r;
}

// ---------------- release/acquire grid-barrier primitives ----------------
__device__ __forceinline__ unsigned ld_acq(const unsigned* p) {
    unsigned v;
    asm volatile("ld.acquire.gpu.global.u32 %0, [%1];" : "=r"(v) : "l"(p) : "memory");
    return v;
}
__device__ __forceinline__ void red_rel(unsigned* p) {
    asm volatile("red.release.gpu.global.add.u32 [%0], 1;" :: "l"(p) : "memory");
}

// ---------------- K_pre: init + embedding ----------------
__global__ void __launch_bounds__(256) k_pre(const int* __restrict__ seq,
                      const float* __restrict__ last_hidden,
                      const float* __restrict__ emb_table,
                      const float* __restrict__ b_ih,
                      const float* __restrict__ b_concat,
                      const float* __restrict__ b_out,
                      float* __restrict__ out)
{
    int blk = blockIdx.x, t = threadIdx.x;
    if (blk < 64) {
        int b = blk;
        int row = seq[b];
        ((float4*)(g_emb + b * H_))[t] = ((const float4*)(emb_table + (size_t)row * H_))[t];
        float4* gi4 = (float4*)(g_gi + b * 3 * H_);
        const float4* bi4 = (const float4*)b_ih;
        for (int i = t; i < 768; i += 256) gi4[i] = bi4[i];
        ((float4*)(g_pre + b * H_))[t] = ((const float4*)b_concat)[t];
    } else if (blk < 128) {
        int b = blk - 64;
        float4* d = (float4*)(out + (size_t)b * V_);
        const float4* bo = (const float4*)b_out;
        for (int i = t; i < V_ / 4; i += 256) d[i] = bo[i];
    } else {
        for (int i = t; i < H_; i += 256) {
            float v = last_hidden[i];
#pragma unroll
            for (int c = 0; c < 8; c++) g_hrep[c][0][i] = v;
            g_ue[i] = 0.f;
        }
        if (t == 0) g_bar = 0u;
    }
}

// ---------------- u_e[k] = sum_h v_attn[h] * W_attn[h][H_+k]  (h-split + atomics) ----------------
__global__ void __launch_bounds__(256) k_ue(const float* __restrict__ W_attn,
                                            const float* __restrict__ v_attn)
{
    int kb = blockIdx.x & 3;          // 4 k blocks of 256
    int hb = blockIdx.x >> 2;         // 16 h blocks of 64
    int k = kb * 256 + threadIdx.x;
    int h0 = hb * 64;
    float acc = 0.f;
#pragma unroll 8
    for (int h = h0; h < h0 + 64; h++)
        acc = fmaf(v_attn[h], W_attn[(size_t)h * (2 * H_) + H_ + k], acc);
    atomicAdd(&g_ue[k], acc);
}

// ---------------- GEMM: C[b][r] += sum_k W[r][k]*E[b][k], regs tile, fma.f32x2 ----------------
// MODE 0: gi      (E=g_emb ldE=1024, C=g_gi  ldC=3072)
// MODE 1: concat  (E=g_cat ldE=2048, C=g_pre ldC=1024)
// MODE 2: out     (E=g_E   ldE=1024, C=Cout  ldC=10000)
template<int MODE, int R>
__global__ void __launch_bounds__(256) k_gemm(const float* __restrict__ W, int lda,
                                              int Rtot, int Ksplit,
                                              float* __restrict__ Cout)
{
    constexpr int KC = 16;
    constexpr int TR = R / 32;
    const float* E; int ldE; float* C; int ldC;
    if constexpr (MODE == 0) { E = g_emb; ldE = H_;     C = g_gi;  ldC = 3 * H_; }
    else if constexpr (MODE == 1) { E = g_cat; ldE = 2 * H_; C = g_pre; ldC = H_; }
    else { E = g_E; ldE = H_; C = Cout; ldC = V_; }

    __shared__ float sWT[KC][R + 4];     // transposed W tile: [k][row]
    __shared__ float sE[KC][64 + 4];     // [k][batch]

    const int r0 = blockIdx.x * R;
    const int k0 = blockIdx.y * Ksplit;
    const int tcol = threadIdx.x & 7;    // 8 batch groups of 8
    const int trow = threadIdx.x >> 3;   // 32 row groups of TR

    unsigned long long acc2[TR][4];
#pragma unroll
    for (int i = 0; i < TR; i++)
#pragma unroll
        for (int j = 0; j < 4; j++) acc2[i][j] = 0ull;

    for (int kc = k0; kc < k0 + Ksplit; kc += KC) {
        // stage W tile (R rows x 16 k), float4 loads, transposed store
#pragma unroll
        for (int q = 0; q < R * KC / 1024; q++) {
            int idx = threadIdx.x + q * 256;
            int rr = idx >> 2;
            int kq = (idx & 3) * 4;
            int gr = r0 + rr;
            float4 v = (gr < Rtot) ? *(const float4*)&W[(size_t)gr * lda + kc + kq]
                                   : make_float4(0.f, 0.f, 0.f, 0.f);
            sWT[kq + 0][rr] = v.x; sWT[kq + 1][rr] = v.y;
            sWT[kq + 2][rr] = v.z; sWT[kq + 3][rr] = v.w;
        }
        // stage E tile (64 b x 16 k)
        {
            int bb = threadIdx.x >> 2;
            int kq = (threadIdx.x & 3) * 4;
            float4 v = *(const float4*)&E[bb * ldE + kc + kq];
            sE[kq + 0][bb] = v.x; sE[kq + 1][bb] = v.y;
            sE[kq + 2][bb] = v.z; sE[kq + 3][bb] = v.w;
        }
        __syncthreads();
#pragma unroll
        for (int kk = 0; kk < KC; kk++) {
            float a[TR];
#pragma unroll
            for (int q = 0; q < TR; q += 4)
                *(float4*)&a[q] = *(const float4*)&sWT[kk][trow * TR + q];
            ulonglong2 q0 = *(const ulonglong2*)&sE[kk][tcol * 8];
            ulonglong2 q1 = *(const ulonglong2*)&sE[kk][tcol * 8 + 4];
            unsigned long long b2[4] = {q0.x, q0.y, q1.x, q1.y};
#pragma unroll
            for (int i = 0; i < TR; i++) {
                unsigned long long ua = pack2(a[i], a[i]);
#pragma unroll
                for (int j = 0; j < 4; j++) fma2(acc2[i][j], ua, b2[j]);
            }
        }
        __syncthreads();
    }
#pragma unroll
    for (int i = 0; i < TR; i++) {
        int gr = r0 + trow * TR + i;
        if (gr < Rtot) {
#pragma unroll
            for (int j = 0; j < 4; j++) {
                float2 v = unpack2(acc2[i][j]);
                atomicAdd(&C[(size_t)(tcol * 8 + 2 * j) * ldC + gr], v.x);
                atomicAdd(&C[(size_t)(tcol * 8 + 2 * j + 1) * ldC + gr], v.y);
            }
        }
    }
}

// ---------------- persistent GRU: packed-f32x2 dot, replicated h, rel/acq barrier ----------------
__global__ void __launch_bounds__(256) k_gru(const float* __restrict__ W_hh,
                                             const float* __restrict__ b_hh,
                                             float* __restrict__ out)
{
    __shared__ float sH[H_];
    const int t = threadIdx.x, w = t >> 5, lane = t & 31;
    const int j = blockIdx.x * 8 + w;
    const int rep = blockIdx.x & 7;

    // this warp's three weight rows, register-resident as f32x2 pairs (96 regs/lane)
    unsigned long long wr2[16], wz2[16], wn2[16];
    {
        const float4* Wr4 = (const float4*)(W_hh + (size_t)j * H_);
        const float4* Wz4 = (const float4*)(W_hh + (size_t)(H_ + j) * H_);
        const float4* Wn4 = (const float4*)(W_hh + (size_t)(2 * H_ + j) * H_);
#pragma unroll
        for (int i = 0; i < 8; i++) {
            float4 v;
            v = Wr4[lane + i * 32]; wr2[2*i] = pack2(v.x, v.y); wr2[2*i+1] = pack2(v.z, v.w);
            v = Wz4[lane + i * 32]; wz2[2*i] = pack2(v.x, v.y); wz2[2*i+1] = pack2(v.z, v.w);
            v = Wn4[lane + i * 32]; wn2[2*i] = pack2(v.x, v.y); wn2[2*i+1] = pack2(v.z, v.w);
        }
    }
    const float bhr = b_hh[j], bhz = b_hh[H_ + j], bhn = b_hh[2 * H_ + j];
    const float4* sH4 = (const float4*)sH;

    // gi for step 0 prefetched before the loop
    float gir = g_gi[j], giz = g_gi[H_ + j], gin = g_gi[2 * H_ + j];

    for (int b = 0; b < B_; b++) {
        // stage this CTA's h replica (L2, written by other SMs)
        ((float4*)sH)[t] = __ldcg((const float4*)(&g_hrep[rep][b & 1][0]) + t);
        __syncthreads();

        unsigned long long ara = 0ull, arb = 0ull, aza = 0ull, azb = 0ull, ana = 0ull, anb = 0ull;
#pragma unroll
        for (int i = 0; i < 8; i++) {
            float4 h4 = sH4[lane + i * 32];
            unsigned long long ha = pack2(h4.x, h4.y), hb = pack2(h4.z, h4.w);
            fma2(ara, wr2[2*i], ha); fma2(arb, wr2[2*i+1], hb);
            fma2(aza, wz2[2*i], ha); fma2(azb, wz2[2*i+1], hb);
            fma2(ana, wn2[2*i], ha); fma2(anb, wn2[2*i+1], hb);
        }
        float2 ra = unpack2(ara), rb = unpack2(arb);
        float2 za = unpack2(aza), zb = unpack2(azb);
        float2 na = unpack2(ana), nb = unpack2(anb);
        float ar = (ra.x + ra.y) + (rb.x + rb.y);
        float az = (za.x + za.y) + (zb.x + zb.y);
        float an = (na.x + na.y) + (nb.x + nb.y);
#pragma unroll
        for (int off = 16; off; off >>= 1) {
            ar += __shfl_down_sync(0xffffffffu, ar, off);
            az += __shfl_down_sync(0xffffffffu, az, off);
            an += __shfl_down_sync(0xffffffffu, an, off);
        }
        float hn = 0.f;
        if (lane == 0) {
            // fast activations on the serial critical path (err ~1e-6, budget 1e-3)
            float r = 1.f / (1.f + __expf(-(gir + ar + bhr)));
            float z = 1.f / (1.f + __expf(-(giz + az + bhz)));
            float narg = gin + r * (an + bhn);
            float n = 2.f / (1.f + __expf(-2.f * narg)) - 1.f;   // tanh
            float hp = sH[j];
            hn = (1.f - z) * n + z * hp;
            g_cat[b * 2 * H_ + j] = hn;
            if (b == B_ - 1) out[B_ * V_ + j] = hn;   // hidden output
        }
        if (b == B_ - 1) break;                        // no barrier after last step
        // broadcast hn, lanes 0-7 store the 8 replicas
        float hnb = __shfl_sync(0xffffffffu, hn, 0);
        if (lane < 8) g_hrep[lane][(b + 1) & 1][j] = hnb;
        // prefetch next step's gi BEFORE the barrier (off critical path)
        {
            const float* gib = g_gi + (b + 1) * 3 * H_;
            gir = gib[j]; giz = gib[H_ + j]; gin = gib[2 * H_ + j];
        }
        __syncthreads();                               // all stores done before release
        if (t == 0) {
            red_rel(&g_bar);                           // release: publishes block's h stores
            unsigned target = (unsigned)(b + 1) * GRU_BLOCKS;
            while (ld_acq(&g_bar) < target) { }        // acquire: sees peers' h stores
        }
        __syncthreads();
    }
}

// ---------------- single-pass flash attention: partials per (b, squad) ----------------
__global__ void __launch_bounds__(256) k_att1(const float* __restrict__ enc)
{
    int bx = blockIdx.x;
    int b = bx >> 3, sq = bx & 7;
    int t = threadIdx.x, w = t >> 5, lane = t & 31;
    int s0 = sq * 32;

    float4 ue = ((const float4*)g_ue)[t];
    float4 ctx = make_float4(0.f, 0.f, 0.f, 0.f);
    float m = -1e30f, sum = 0.f;
    __shared__ float r0s[8], r1s[8];

    const float* base = enc + b * H_;
    for (int s = s0; s < s0 + 32; s += 2) {
        float4 e0 = __ldcg((const float4*)(base + (size_t)s * (B_ * H_)) + t);
        float4 e1 = __ldcg((const float4*)(base + (size_t)(s + 1) * (B_ * H_)) + t);
        float d0 = e0.x * ue.x + e0.y * ue.y + e0.z * ue.z + e0.w * ue.w;
        float d1 = e1.x * ue.x + e1.y * ue.y + e1.z * ue.z + e1.w * ue.w;
#pragma unroll
        for (int off = 16; off; off >>= 1) {
            d0 += __shfl_xor_sync(0xffffffffu, d0, off);
            d1 += __shfl_xor_sync(0xffffffffu, d1, off);
        }
        if (lane == 0) { r0s[w] = d0; r1s[w] = d1; }
        __syncthreads();
        float sc0 = (r0s[0] + r0s[1]) + (r0s[2] + r0s[3]) + (r0s[4] + r0s[5]) + (r0s[6] + r0s[7]);
        float sc1 = (r1s[0] + r1s[1]) + (r1s[2] + r1s[3]) + (r1s[4] + r1s[5]) + (r1s[6] + r1s[7]);
        __syncthreads();
        if (t == 0) g_scores[b * S_ + s] = sc0;
        if (t == 1) g_scores[b * S_ + s + 1] = sc1;
        // online softmax update x2
        float mn = fmaxf(m, sc0);
        float a = __expf(m - mn), w0 = __expf(sc0 - mn);
        sum = sum * a + w0;
        ctx.x = ctx.x * a + w0 * e0.x; ctx.y = ctx.y * a + w0 * e0.y;
        ctx.z = ctx.z * a + w0 * e0.z; ctx.w = ctx.w * a + w0 * e0.w;
        m = mn;
        mn = fmaxf(m, sc1);
        a = __expf(m - mn); float w1 = __expf(sc1 - mn);
        sum = sum * a + w1;
        ctx.x = ctx.x * a + w1 * e1.x; ctx.y = ctx.y * a + w1 * e1.y;
        ctx.z = ctx.z * a + w1 * e1.z; ctx.w = ctx.w * a + w1 * e1.w;
        m = mn;
    }
    ((float4*)(g_ctxp + (size_t)bx * H_))[t] = ctx;
    if (t == 0) { g_msum[bx * 2] = m; g_msum[bx * 2 + 1] = sum; }
}

// ---------------- attention combine: per b, merge 8 partials; write ctx + weights ----------------
__global__ void __launch_bounds__(256) k_att2(float* __restrict__ out)
{
    int b = blockIdx.x, t = threadIdx.x;
    __shared__ float sm_[8], ss_[8];
    if (t < 8) { sm_[t] = g_msum[(b * 8 + t) * 2]; ss_[t] = g_msum[(b * 8 + t) * 2 + 1]; }
    __syncthreads();
    float m = sm_[0];
#pragma unroll
    for (int i = 1; i < 8; i++) m = fmaxf(m, sm_[i]);
    float scl[8]; float S = 0.f;
#pragma unroll
    for (int i = 0; i < 8; i++) { scl[i] = __expf(sm_[i] - m); S = fmaf(ss_[i], scl[i], S); }
    float inv = 1.f / S;

    float4 acc = make_float4(0.f, 0.f, 0.f, 0.f);
#pragma unroll
    for (int i = 0; i < 8; i++) {
        float4 p = ((const float4*)(g_ctxp + (size_t)(b * 8 + i) * H_))[t];
        acc.x = fmaf(p.x, scl[i], acc.x); acc.y = fmaf(p.y, scl[i], acc.y);
        acc.z = fmaf(p.z, scl[i], acc.z); acc.w = fmaf(p.w, scl[i], acc.w);
    }
    acc.x *= inv; acc.y *= inv; acc.z *= inv; acc.w *= inv;
    ((float4*)(g_cat + b * 2 * H_ + H_))[t] = acc;

    // attn_weights output
    float sc = g_scores[b * S_ + t];
    out[B_ * V_ + H_ + b * S_ + t] = __expf(sc - m) * inv;
}

// ---------------- tanh staging: g_E = tanh(g_pre), computed once ----------------
__global__ void __launch_bounds__(256) k_tanh()
{
    int idx = blockIdx.x * 256 + threadIdx.x;     // 16384 float4s
    float4 v = ((const float4*)g_pre)[idx];
    v.x = tanhf(v.x); v.y = tanhf(v.y); v.z = tanhf(v.z); v.w = tanhf(v.w);
    ((float4*)g_E)[idx] = v;
}

extern "C" void kernel_launch(void* const* d_in, const int* in_sizes, int n_in,
                              void* d_out, int out_size)
{
    const int*   seq         = (const int*)d_in[0];
    const float* last_hidden = (const float*)d_in[1];
    const float* enc         = (const float*)d_in[2];
    const float* emb_table   = (const float*)d_in[3];
    const float* W_ih        = (const float*)d_in[4];
    const float* W_hh        = (const float*)d_in[5];
    const float* b_ih        = (const float*)d_in[6];
    const float* b_hh        = (const float*)d_in[7];
    const float* W_attn      = (const float*)d_in[8];
    /* d_in[9] = b_attn: dropped — softmax is shift-invariant */
    const float* v_attn      = (const float*)d_in[10];
    const float* W_concat    = (const float*)d_in[11];
    const float* b_concat    = (const float*)d_in[12];
    const float* W_out       = (const float*)d_in[13];
    const float* b_out       = (const float*)d_in[14];
    float* out = (float*)d_out;

    // 0: init + embedding + h0 replicas + barrier/ue reset
    k_pre<<<129, 256>>>(seq, last_hidden, emb_table, b_ih, b_concat, b_out, out);

    // 1: u_e (parallel h-split)
    k_ue<<<64, 256>>>(W_attn, v_attn);

    // 2: gi = emb @ W_ih^T (+b_ih pre-init): 24 rb(128) x splitK 4 (k=256) = 96 CTAs
    k_gemm<0, 128><<<dim3(24, 4), 256>>>(W_ih, H_, 3 * H_, 256, nullptr);

    // 3: sequential GRU recurrence  <-- ncu profiles launch index 3
    k_gru<<<GRU_BLOCKS, 256>>>(W_hh, b_hh, out);

    // 4-5: single-pass attention (enc read once) + combine
    k_att1<<<512, 256>>>(enc);
    k_att2<<<64, 256>>>(out);

    // 6: concat preactivation: g_pre += [rnn|ctx] @ W_concat^T: 8 rb x splitK 16 (k=128) = 128 CTAs
    k_gemm<1, 128><<<dim3(8, 16), 256>>>(W_concat, 2 * H_, H_, 128, nullptr);

    // 7: tanh once
    k_tanh<<<64, 256>>>();

    // 8: logits: out += g_E @ W_out^T: 79 rb(128) x splitK 4 (k=256) = 316 CTAs
    k_gemm<2, 128><<<dim3(79, 4), 256>>>(W_out, H_, V_, 256, out);
}